// round 5
// baseline (speedup 1.0000x reference)
#include <cuda_runtime.h>

#define B_ 2
#define C_ 128
#define T_ 512
#define F_ 64
#define H_ 32
#define D_ 32

// Scratch (allocation-free rule: __device__ globals)
__device__ float g_xm1[B_*H_*T_*F_];   // (b,h,t,f)
__device__ float g_xf1[B_*H_*T_*F_];
__device__ float g_corr[B_*H_*T_*D_];  // (b,h,t,d)
__device__ float g_w[B_*T_*D_];

// ---------------------------------------------------------------------------
// Kernel 1: xm1[b,h,t,f] = sum_c xm[b,c,t,f]*w1[c,h] + b1[h]  (and xf1/w2/b2)
// Block = one (b,t). 256 threads: thread owns (f, 8 consecutive h).
// Double-buffered smem chunks of 16 c-rows, float4 LDG prefetch.
// ---------------------------------------------------------------------------
__global__ __launch_bounds__(256) void proj_kernel(
    const float* __restrict__ xm, const float* __restrict__ xf,
    const float* __restrict__ w1, const float* __restrict__ b1,
    const float* __restrict__ w2, const float* __restrict__ b2)
{
    __shared__ float w1s[C_][H_];         // 16KB
    __shared__ float w2s[C_][H_];         // 16KB
    __shared__ float xs[2][2][16][F_];    // 16KB double-buffered

    const int b = blockIdx.x >> 9;
    const int t = blockIdx.x & 511;
    const int tid = threadIdx.x;

    for (int i = tid; i < C_*H_; i += 256) {
        w1s[i >> 5][i & 31] = w1[i];
        w2s[i >> 5][i & 31] = w2[i];
    }

    const int f  = tid & 63;
    const int hb = (tid >> 6) * 8;
    const int ccl = tid >> 4;          // 0..15 : c-row within chunk
    const int ff4 = (tid & 15) * 4;    // float4 f offset

    float accm[8], accf[8];
    #pragma unroll
    for (int i = 0; i < 8; i++) { accm[i] = b1[hb + i]; accf[i] = b2[hb + i]; }

    const float* xmp = xm + (size_t)b * C_ * T_ * F_ + (size_t)t * F_;
    const float* xfp = xf + (size_t)b * C_ * T_ * F_ + (size_t)t * F_;

    // prefetch chunk 0
    float4 rm = *(const float4*)(xmp + (size_t)ccl * T_ * F_ + ff4);
    float4 rf = *(const float4*)(xfp + (size_t)ccl * T_ * F_ + ff4);

    for (int c0 = 0; c0 < C_; c0 += 16) {
        const int buf = (c0 >> 4) & 1;
        *(float4*)&xs[buf][0][ccl][ff4] = rm;
        *(float4*)&xs[buf][1][ccl][ff4] = rf;
        __syncthreads();
        if (c0 < C_ - 16) {
            rm = *(const float4*)(xmp + (size_t)(c0 + 16 + ccl) * T_ * F_ + ff4);
            rf = *(const float4*)(xfp + (size_t)(c0 + 16 + ccl) * T_ * F_ + ff4);
        }
        #pragma unroll
        for (int cc = 0; cc < 16; cc++) {
            float vm = xs[buf][0][cc][f];
            float vf = xs[buf][1][cc][f];
            float4 wA = *(const float4*)&w1s[c0 + cc][hb];
            float4 wB = *(const float4*)&w1s[c0 + cc][hb + 4];
            float4 uA = *(const float4*)&w2s[c0 + cc][hb];
            float4 uB = *(const float4*)&w2s[c0 + cc][hb + 4];
            accm[0] += vm * wA.x; accm[1] += vm * wA.y;
            accm[2] += vm * wA.z; accm[3] += vm * wA.w;
            accm[4] += vm * wB.x; accm[5] += vm * wB.y;
            accm[6] += vm * wB.z; accm[7] += vm * wB.w;
            accf[0] += vf * uA.x; accf[1] += vf * uA.y;
            accf[2] += vf * uA.z; accf[3] += vf * uA.w;
            accf[4] += vf * uB.x; accf[5] += vf * uB.y;
            accf[6] += vf * uB.z; accf[7] += vf * uB.w;
        }
    }

    size_t ob = ((size_t)(b * H_ + hb) * T_ + t) * F_ + f;
    #pragma unroll
    for (int i = 0; i < 8; i++) {
        g_xm1[ob + (size_t)i * T_ * F_] = accm[i];
        g_xf1[ob + (size_t)i * T_ * F_] = accf[i];
    }
}

// ---------------------------------------------------------------------------
// Kernel 2: corr[b,h,t,d] = sum_f xm1[b,h,t,f] * xf1[b,h,t+d-31,f]
// Block = (b,h,t-tile of 64). Thread owns (t-local, 8 consecutive d).
// Row pad 68 floats: LDS.128 column access is phase-conflict-free (16B steps).
// ---------------------------------------------------------------------------
__global__ __launch_bounds__(256) void corr_kernel()
{
    __shared__ float xm1s[64][68];
    __shared__ float xfw[95][68];

    const int bid = blockIdx.x;
    const int tt = bid & 7;
    const int h  = (bid >> 3) & (H_ - 1);
    const int b  = bid >> 8;
    const int t0 = tt * 64;
    const int tid = threadIdx.x;

    const float* mp = g_xm1 + (size_t)(b * H_ + h) * T_ * F_;
    const float* fp = g_xf1 + (size_t)(b * H_ + h) * T_ * F_;

    // vectorized fills
    for (int i = tid; i < 64 * 16; i += 256) {
        int r = i >> 4, f4 = (i & 15) * 4;
        *(float4*)&xm1s[r][f4] = *(const float4*)(mp + (size_t)(t0 + r) * F_ + f4);
    }
    for (int i = tid; i < 95 * 16; i += 256) {
        int r = i >> 4, f4 = (i & 15) * 4;
        int tg = t0 + r - 31;
        float4 v = make_float4(0.f, 0.f, 0.f, 0.f);
        if (tg >= 0) v = *(const float4*)(fp + (size_t)tg * F_ + f4);
        *(float4*)&xfw[r][f4] = v;
    }
    __syncthreads();

    const int tl = tid & 63;
    const int db = (tid >> 6) * 8;

    float acc[8];
    #pragma unroll
    for (int k = 0; k < 8; k++) acc[k] = 0.f;

    #pragma unroll
    for (int f4 = 0; f4 < F_; f4 += 4) {
        float4 m = *(const float4*)&xm1s[tl][f4];
        #pragma unroll
        for (int k = 0; k < 8; k++) {
            float4 v = *(const float4*)&xfw[tl + db + k][f4];
            acc[k] += m.x * v.x + m.y * v.y + m.z * v.z + m.w * v.w;
        }
    }

    float* cp = g_corr + ((size_t)(b * H_ + h) * T_ + t0 + tl) * D_ + db;
    *(float4*)&cp[0] = make_float4(acc[0], acc[1], acc[2], acc[3]);
    *(float4*)&cp[4] = make_float4(acc[4], acc[5], acc[6], acc[7]);
}

// ---------------------------------------------------------------------------
// Kernel 3: conv(5x3 over h) + bias + causal mask + softmax(d)
// Block = 2 t values; 4 warps per t split the h-sum (8 h each), smem reduce,
// warps 0/4 do the softmax. Grid = B*T/2 = 512 blocks.
// ---------------------------------------------------------------------------
__global__ __launch_bounds__(256) void conv_softmax_kernel(
    const float* __restrict__ wc, const float* __restrict__ bc)
{
    __shared__ float wcs[H_ * 15];
    __shared__ float part[8][32];
    const int tid = threadIdx.x;
    for (int i = tid; i < H_ * 15; i += 256) wcs[i] = wc[i];
    __syncthreads();

    const int lane = tid & 31;
    const int wid  = tid >> 5;          // 0..7
    const int sub  = wid >> 2;          // which of the 2 t's
    const int hq   = (wid & 3) * 8;     // h base for this warp
    const int idx  = blockIdx.x * 2 + sub;
    const int b = idx >> 9;
    const int t = idx & 511;

    float acc = 0.f;
    #pragma unroll
    for (int hh = 0; hh < 8; hh++) {
        const int h = hq + hh;
        const float* cp = g_corr + (size_t)(b * H_ + h) * T_ * D_;
        const float* wr = &wcs[h * 15];
        #pragma unroll
        for (int kt = 0; kt < 5; kt++) {
            int ti = t + kt - 3;
            if (ti >= 0 && ti < T_) {
                float v  = cp[(size_t)ti * D_ + lane];
                float vm = __shfl_up_sync(0xffffffffu, v, 1);
                float vp = __shfl_down_sync(0xffffffffu, v, 1);
                if (lane == 0)  vm = 0.f;
                if (lane == 31) vp = 0.f;
                acc += wr[kt*3 + 0] * vm + wr[kt*3 + 1] * v + wr[kt*3 + 2] * vp;
            }
        }
    }
    part[wid][lane] = acc;
    __syncthreads();

    if ((wid & 3) == 0) {
        float a = part[wid][lane] + part[wid+1][lane]
                + part[wid+2][lane] + part[wid+3][lane] + bc[0];
        if (t + lane < D_ - 1) a = -10000000000000.0f;

        float m = a;
        #pragma unroll
        for (int o = 16; o > 0; o >>= 1) m = fmaxf(m, __shfl_xor_sync(0xffffffffu, m, o));
        float e = expf(a - m);
        float s = e;
        #pragma unroll
        for (int o = 16; o > 0; o >>= 1) s += __shfl_xor_sync(0xffffffffu, s, o);

        g_w[((size_t)b * T_ + t) * D_ + lane] = e / s;
    }
}

// ---------------------------------------------------------------------------
// Kernel 4: out[b,c,t,f] = sum_d w[b,t,d] * xf[b,c,t+d-31,f]
// Block = (b,c,t-tile of 64). Thread owns (4 t-rows, float4 of f).
// Fully unrolled sliding 4-row register window; float4 ws loads.
// ---------------------------------------------------------------------------
__global__ __launch_bounds__(256) void out_kernel(
    const float* __restrict__ xf, float* __restrict__ out)
{
    __shared__ float xfw[95][68];   // 25.8KB
    __shared__ float ws[64][36];    // 9.2KB, 16B-aligned rows

    const int bid = blockIdx.x;
    const int tt = bid & 7;
    const int c  = (bid >> 3) & (C_ - 1);
    const int b  = bid >> 10;
    const int t0 = tt * 64;
    const int tid = threadIdx.x;

    const float* xfp = xf + (size_t)(b * C_ + c) * T_ * F_;

    for (int i = tid; i < 95 * 16; i += 256) {
        int r = i >> 4, f4v = (i & 15) * 4;
        int tg = t0 + r - 31;
        float4 v = make_float4(0.f, 0.f, 0.f, 0.f);
        if (tg >= 0) v = *(const float4*)(xfp + (size_t)tg * F_ + f4v);
        *(float4*)&xfw[r][f4v] = v;
    }
    for (int i = tid; i < 64 * 8; i += 256) {
        int r = i >> 3, d4 = (i & 7) * 4;
        *(float4*)&ws[r][d4] = *(const float4*)(g_w + ((size_t)b * T_ + t0 + r) * D_ + d4);
    }
    __syncthreads();

    const int f4  = (tid & 15) * 4;
    const int tlb = (tid >> 4) * 4;

    float4 acc0 = {0,0,0,0}, acc1 = {0,0,0,0}, acc2 = {0,0,0,0}, acc3 = {0,0,0,0};

    float4 x0 = *(const float4*)&xfw[tlb + 0][f4];
    float4 x1 = *(const float4*)&xfw[tlb + 1][f4];
    float4 x2 = *(const float4*)&xfw[tlb + 2][f4];
    float4 x3 = *(const float4*)&xfw[tlb + 3][f4];

    #pragma unroll
    for (int d0 = 0; d0 < D_; d0 += 4) {
        float4 wv0 = *(const float4*)&ws[tlb + 0][d0];
        float4 wv1 = *(const float4*)&ws[tlb + 1][d0];
        float4 wv2 = *(const float4*)&ws[tlb + 2][d0];
        float4 wv3 = *(const float4*)&ws[tlb + 3][d0];

        #pragma unroll
        for (int s = 0; s < 4; s++) {
            const int d = d0 + s;
            float w0 = (s == 0) ? wv0.x : (s == 1) ? wv0.y : (s == 2) ? wv0.z : wv0.w;
            float w1v = (s == 0) ? wv1.x : (s == 1) ? wv1.y : (s == 2) ? wv1.z : wv1.w;
            float w2v = (s == 0) ? wv2.x : (s == 1) ? wv2.y : (s == 2) ? wv2.z : wv2.w;
            float w3v = (s == 0) ? wv3.x : (s == 1) ? wv3.y : (s == 2) ? wv3.z : wv3.w;

            acc0.x += w0 * x0.x; acc0.y += w0 * x0.y; acc0.z += w0 * x0.z; acc0.w += w0 * x0.w;
            acc1.x += w1v * x1.x; acc1.y += w1v * x1.y; acc1.z += w1v * x1.z; acc1.w += w1v * x1.w;
            acc2.x += w2v * x2.x; acc2.y += w2v * x2.y; acc2.z += w2v * x2.z; acc2.w += w2v * x2.w;
            acc3.x += w3v * x3.x; acc3.y += w3v * x3.y; acc3.z += w3v * x3.z; acc3.w += w3v * x3.w;

            if (d < D_ - 1) {
                x0 = x1; x1 = x2; x2 = x3;
                x3 = *(const float4*)&xfw[tlb + d + 4][f4];
            }
        }
    }

    float* op = out + ((size_t)(b * C_ + c) * T_ + t0) * F_;
    *(float4*)&op[(size_t)(tlb + 0) * F_ + f4] = acc0;
    *(float4*)&op[(size_t)(tlb + 1) * F_ + f4] = acc1;
    *(float4*)&op[(size_t)(tlb + 2) * F_ + f4] = acc2;
    *(float4*)&op[(size_t)(tlb + 3) * F_ + f4] = acc3;
}

// ---------------------------------------------------------------------------
extern "C" void kernel_launch(void* const* d_in, const int* in_sizes, int n_in,
                              void* d_out, int out_size)
{
    const float* xm = (const float*)d_in[0];
    const float* xf = (const float*)d_in[1];
    const float* w1 = (const float*)d_in[2];
    const float* b1 = (const float*)d_in[3];
    const float* w2 = (const float*)d_in[4];
    const float* b2 = (const float*)d_in[5];
    const float* wc = (const float*)d_in[6];
    const float* bc = (const float*)d_in[7];
    float* out = (float*)d_out;

    proj_kernel<<<B_ * T_, 256>>>(xm, xf, w1, b1, w2, b2);
    corr_kernel<<<B_ * H_ * (T_ / 64), 256>>>();
    conv_softmax_kernel<<<B_ * T_ / 2, 256>>>(wc, bc);
    out_kernel<<<B_ * C_ * (T_ / 64), 256>>>(xf, out);
}